// round 15
// baseline (speedup 1.0000x reference)
#include <cuda_runtime.h>
#include <cuda_bf16.h>
#include <math.h>
#include <stdint.h>

// Problem constants
#define B_    4096
#define DIN_  2048
#define DOUT_ 128
#define N_    8192   // 2*B_

// zn pre-scale: dot(zn'_i, zn'_j) = (2/T_temp)*log2(e) * cos_ij  (T=0.5)
// so exp(sim/T) = 2^dot  -- epilogue needs only EX2, no scaling FMULs.
#define ZN_SCALE 1.69864122f    // sqrt(2 * log2(e))
#define LN2_     0.69314718055994531f

// Scratch (device globals -- no allocation allowed)
__device__ __nv_bfloat16 g_znb[N_ * DOUT_];    // scaled normalized reps, bf16
__device__ __nv_bfloat16 g_wb[DOUT_ * DIN_];   // W in bf16, 512 KB
__device__ float g_h0[N_ * DOUT_];             // split-K partial 0, fp32, 4 MB
__device__ float g_h1[N_ * DOUT_];             // split-K partial 1, fp32, 4 MB
__device__ float g_rowsum_part[32 * N_];       // per-(jsplit,warpcol) partials
__device__ float g_pos[N_];                    // positive-pair logits (base-2 units)
__device__ double g_loss_part[64];             // per-CTA partial losses

__device__ __forceinline__ uint32_t sptr(const void* p) {
    return (uint32_t)__cvta_generic_to_shared(p);
}

__device__ __forceinline__ float ex2f(float x) {
    float r;
    asm("ex2.approx.ftz.f32 %0, %1;" : "=f"(r) : "f"(x));
    return r;
}

__device__ __forceinline__ void ldsm_x4(uint32_t addr, uint32_t& r0, uint32_t& r1,
                                        uint32_t& r2, uint32_t& r3) {
    asm volatile("ldmatrix.sync.aligned.m8n8.x4.shared.b16 {%0,%1,%2,%3}, [%4];"
                 : "=r"(r0), "=r"(r1), "=r"(r2), "=r"(r3) : "r"(addr));
}

__device__ __forceinline__ void mma16816(float* c, const uint32_t* a, const uint32_t* b) {
    asm volatile(
        "mma.sync.aligned.m16n8k16.row.col.f32.bf16.bf16.f32 "
        "{%0,%1,%2,%3}, {%4,%5,%6,%7}, {%8,%9}, {%0,%1,%2,%3};"
        : "+f"(c[0]), "+f"(c[1]), "+f"(c[2]), "+f"(c[3])
        : "r"(a[0]), "r"(a[1]), "r"(a[2]), "r"(a[3]), "r"(b[0]), "r"(b[1]));
}

// First-use form: d = a*b + 0 (c is zero; d independent of old acc value).
__device__ __forceinline__ void mma16816_z(float* d, const uint32_t* a, const uint32_t* b) {
    asm volatile(
        "mma.sync.aligned.m16n8k16.row.col.f32.bf16.bf16.f32 "
        "{%0,%1,%2,%3}, {%4,%5,%6,%7}, {%8,%9}, {%10,%11,%12,%13};"
        : "=f"(d[0]), "=f"(d[1]), "=f"(d[2]), "=f"(d[3])
        : "r"(a[0]), "r"(a[1]), "r"(a[2]), "r"(a[3]), "r"(b[0]), "r"(b[1]),
          "f"(0.0f), "f"(0.0f), "f"(0.0f), "f"(0.0f));
}

__device__ __forceinline__ void cpa16(uint32_t smem_addr, const void* gptr) {
    asm volatile("cp.async.cg.shared.global.L2::128B [%0], [%1], 16;"
                 :: "r"(smem_addr), "l"(gptr) : "memory");
}

__device__ __forceinline__ void sts16(uint32_t addr, uint4 v) {
    asm volatile("st.shared.v4.b32 [%0], {%1,%2,%3,%4};"
                 :: "r"(addr), "r"(v.x), "r"(v.y), "r"(v.z), "r"(v.w) : "memory");
}

// ---------------------------------------------------------------------------
// Kernel 0: convert W (fp32) -> g_wb (bf16).
// ---------------------------------------------------------------------------
__global__ __launch_bounds__(256) void wconv_kernel(const float* __restrict__ W)
{
    int idx = blockIdx.x * 256 + threadIdx.x;
    const float4* src = (const float4*)W;
    float4 v0 = src[2 * idx];
    float4 v1 = src[2 * idx + 1];
    __nv_bfloat162 h[4];
    h[0] = __floats2bfloat162_rn(v0.x, v0.y);
    h[1] = __floats2bfloat162_rn(v0.z, v0.w);
    h[2] = __floats2bfloat162_rn(v1.x, v1.y);
    h[3] = __floats2bfloat162_rn(v1.z, v1.w);
    *(uint4*)&g_wb[idx * 8] = *(uint4*)h;
}

// ---------------------------------------------------------------------------
// Kernel 1: split-K=2 partial GEMM: Hpart = relu(Z) @ Wb[:, khalf]^T.
// ---------------------------------------------------------------------------
#define G1_SMEM_BYTES 99328

__global__ __launch_bounds__(256, 2) void gemm1_part_kernel(
    const float* __restrict__ zi, const float* __restrict__ zj)
{
    extern __shared__ __align__(16) unsigned char dynsm[];
    const uint32_t smraw = sptr(dynsm);
    const uint32_t smbase = (smraw + 1023) & ~1023u;
    const uint32_t As[2] = {smbase, smbase + 16384};
    const uint32_t Ws[2] = {smbase + 32768, smbase + 65536};

    const int tid = threadIdx.x;
    const int lane = tid & 31;
    const int warp = tid >> 5;
    const int tile = blockIdx.x & 127;
    const int khalf = blockIdx.x >> 7;
    const int kbase = khalf * 8;
    const int i0 = tile * 64;

    const float* Z = (i0 < B_) ? zi : zj;
    const int zr0 = (i0 < B_) ? i0 : (i0 - B_);

    float acc[4][2][4];
#pragma unroll
    for (int mt = 0; mt < 4; mt++)
#pragma unroll
        for (int nt = 0; nt < 2; nt++)
#pragma unroll
            for (int e = 0; e < 4; e++) acc[mt][nt][e] = 0.0f;

    float4 av[8];

    auto fetch_A = [&](int kc) {
#pragma unroll
        for (int it = 0; it < 4; it++) {
            int e = tid + it * 256;
            int r = e >> 4, c = e & 15;
            const float* src = &Z[(size_t)(zr0 + r) * DIN_ + kc * 128 + c * 8];
            av[2 * it]     = *(const float4*)src;
            av[2 * it + 1] = *(const float4*)(src + 4);
        }
    };
    auto store_A = [&](int stg) {
#pragma unroll
        for (int it = 0; it < 4; it++) {
            int e = tid + it * 256;
            int r = e >> 4, c = e & 15;
            float4 v0 = av[2 * it], v1 = av[2 * it + 1];
            __nv_bfloat162 h[4];
            h[0] = __floats2bfloat162_rn(fmaxf(v0.x, 0.f), fmaxf(v0.y, 0.f));
            h[1] = __floats2bfloat162_rn(fmaxf(v0.z, 0.f), fmaxf(v0.w, 0.f));
            h[2] = __floats2bfloat162_rn(fmaxf(v1.x, 0.f), fmaxf(v1.y, 0.f));
            h[3] = __floats2bfloat162_rn(fmaxf(v1.z, 0.f), fmaxf(v1.w, 0.f));
            sts16(As[stg] + r * 256 + ((c ^ (r & 7)) << 4), *(uint4*)h);
        }
    };
    auto load_W = [&](int kc, int stg) {
#pragma unroll
        for (int it = 0; it < 8; it++) {
            int e = tid + it * 256;
            int r = e >> 4, c = e & 15;
            cpa16(Ws[stg] + r * 256 + ((c ^ (r & 7)) << 4),
                  &g_wb[(size_t)r * DIN_ + kc * 128 + c * 8]);
        }
        asm volatile("cp.async.commit_group;" ::: "memory");
    };

    fetch_A(kbase);
    load_W(kbase, 0);
    store_A(0);

    for (int kc2 = 0; kc2 < 8; kc2++) {
        const int stg = kc2 & 1;
        asm volatile("cp.async.wait_group 0;" ::: "memory");
        __syncthreads();

        if (kc2 + 1 < 8) {
            fetch_A(kbase + kc2 + 1);
            load_W(kbase + kc2 + 1, stg ^ 1);
        }

        const uint32_t Abase = As[stg], Wbase = Ws[stg];
#pragma unroll
        for (int s = 0; s < 8; s++) {
            uint32_t a[4][4];
#pragma unroll
            for (int mt = 0; mt < 4; mt++) {
                int rloc = 16 * mt + (lane & 15);
                int ch = 2 * s + (lane >> 4);
                uint32_t ad = Abase + rloc * 256 + ((ch ^ (rloc & 7)) << 4);
                ldsm_x4(ad, a[mt][0], a[mt][1], a[mt][2], a[mt][3]);
            }
            uint32_t b[2][2];
            {
                int nloc = 16 * warp + (lane & 7) + ((lane >> 4) << 3);
                int ch = 2 * s + ((lane >> 3) & 1);
                uint32_t ad = Wbase + nloc * 256 + ((ch ^ (nloc & 7)) << 4);
                ldsm_x4(ad, b[0][0], b[0][1], b[1][0], b[1][1]);
            }
#pragma unroll
            for (int mt = 0; mt < 4; mt++)
#pragma unroll
                for (int nt = 0; nt < 2; nt++)
                    mma16816(acc[mt][nt], a[mt], b[nt]);
        }

        if (kc2 + 1 < 8) store_A(stg ^ 1);
    }

    float* Hp = khalf ? g_h1 : g_h0;
#pragma unroll
    for (int mt = 0; mt < 4; mt++)
#pragma unroll
        for (int nt = 0; nt < 2; nt++) {
            int r0 = i0 + 16 * mt + (lane >> 2);
            int c0 = 16 * warp + 8 * nt + 2 * (lane & 3);
            *(float2*)&Hp[(size_t)r0 * DOUT_ + c0] =
                make_float2(acc[mt][nt][0], acc[mt][nt][1]);
            *(float2*)&Hp[(size_t)(r0 + 8) * DOUT_ + c0] =
                make_float2(acc[mt][nt][2], acc[mt][nt][3]);
        }
}

// ---------------------------------------------------------------------------
// Kernel 1b: combine partials + bias, row-normalize, scale by ZN_SCALE.
// ---------------------------------------------------------------------------
__global__ __launch_bounds__(256) void hnorm_kernel(const float* __restrict__ bias)
{
    const int lane = threadIdx.x & 31;
    const int warp = threadIdx.x >> 5;
    const int row = blockIdx.x * 8 + warp;

    float hx[4];
    float ss = 0.0f;
#pragma unroll
    for (int q = 0; q < 2; q++) {
        int c = 2 * lane + 64 * q;
        float2 a = *(const float2*)&g_h0[(size_t)row * DOUT_ + c];
        float2 b = *(const float2*)&g_h1[(size_t)row * DOUT_ + c];
        float2 bb = *(const float2*)&bias[c];
        float x = a.x + b.x + bb.x;
        float y = a.y + b.y + bb.y;
        hx[2 * q] = x; hx[2 * q + 1] = y;
        ss += x * x + y * y;
    }
#pragma unroll
    for (int m = 16; m > 0; m >>= 1)
        ss += __shfl_xor_sync(0xffffffffu, ss, m);
    float inv = ZN_SCALE / fmaxf(sqrtf(ss), 1e-8f);
#pragma unroll
    for (int q = 0; q < 2; q++) {
        int c = 2 * lane + 64 * q;
        *(__nv_bfloat162*)&g_znb[(size_t)row * DOUT_ + c] =
            __floats2bfloat162_rn(hx[2 * q] * inv, hx[2 * q + 1] * inv);
    }
}

// ---------------------------------------------------------------------------
// Kernel 2: sim rowsums. Tile MMA split into two n-half passes so the EX2
// epilogue of one half overlaps (register-independent) the MMA of the next:
//   passA(jt)  [writes nt0,1] || EX2 of prev tile's nt2,3
//   passB(jt)  [writes nt2,3] || EX2 of this tile's nt0,1
// First-use MMAs take c=0 (no acc zero-init). Diag/pos tiles: compare path.
// ---------------------------------------------------------------------------
#define SIM_SMEM_BYTES 99328   // 1KB align slack + 3 x 32KB

__global__ __launch_bounds__(256, 2) void sim_rowsum_kernel()
{
    extern __shared__ __align__(16) unsigned char dynsm[];
    const uint32_t smraw = sptr(dynsm);
    const uint32_t smbase = (smraw + 1023) & ~1023u;
    const uint32_t Abase = smbase;
    const uint32_t Bb[2] = {smbase + 32768, smbase + 65536};

    const int tid = threadIdx.x;
    const int lane = tid & 31;
    const int warp = tid >> 5;
    const int wr = warp >> 2;
    const int wc = warp & 3;
    const int i0 = blockIdx.x * 128;
    const int jbase = blockIdx.y * 1024;
    const int pos_j0 = (i0 + B_) & (N_ - 1);   // 128-aligned pos-tile start

    // Load A tile (plain LDG + STS; covered by the first barrier)
#pragma unroll
    for (int it = 0; it < 8; it++) {
        int e = tid + it * 256;
        int r = e >> 4, c = e & 15;
        uint4 v = *(const uint4*)&g_znb[(size_t)(i0 + r) * DOUT_ + c * 8];
        *(uint4*)(dynsm + (Abase - smraw) + r * 256 + ((c ^ (r & 7)) << 4)) = v;
    }

    // Hoisted B addressing
    const int br = tid >> 4, bc = tid & 15;
    const __nv_bfloat16* srcB0 = &g_znb[(size_t)(jbase + br) * DOUT_ + bc * 8];
    const uint32_t dstoff = (uint32_t)(br * 256 + ((bc ^ (br & 7)) << 4));

    auto load_B = [&](int jt, int buf) {
        const __nv_bfloat16* s = srcB0 + (size_t)jt * (128 * DOUT_);
        uint32_t d = Bb[buf] + dstoff;
#pragma unroll
        for (int it = 0; it < 8; it++) {
            cpa16(d, s);
            s += 16 * DOUT_;
            d += 16 * 256;
        }
        asm volatile("cp.async.commit_group;" ::: "memory");
    };

    load_B(0, 0);

    float rowacc[8];
#pragma unroll
    for (int x = 0; x < 8; x++) rowacc[x] = 0.0f;

    float acc[4][4][4];   // [mt][nt][e]; halves nt{0,1} / nt{2,3}

    // One n-half MMA pass: p=0 -> nt 0,1 ; p=1 -> nt 2,3. sg==0 uses c=0.
    auto mma_pass = [&](uint32_t Bbase, int p) {
#pragma unroll
        for (int sg = 0; sg < 8; sg++) {
            uint32_t a[4][4];
#pragma unroll
            for (int mt = 0; mt < 4; mt++) {
                int rloc = 64 * wr + 16 * mt + (lane & 15);
                int ch = 2 * sg + (lane >> 4);
                uint32_t ad = Abase + rloc * 256 + ((ch ^ (rloc & 7)) << 4);
                ldsm_x4(ad, a[mt][0], a[mt][1], a[mt][2], a[mt][3]);
            }
            uint32_t b[2][2];
            {
                int nloc = 32 * wc + 16 * p + (lane & 7) + ((lane >> 4) << 3);
                int ch = 2 * sg + ((lane >> 3) & 1);
                uint32_t ad = Bbase + nloc * 256 + ((ch ^ (nloc & 7)) << 4);
                ldsm_x4(ad, b[0][0], b[0][1], b[1][0], b[1][1]);
            }
#pragma unroll
            for (int mt = 0; mt < 4; mt++)
#pragma unroll
                for (int q = 0; q < 2; q++) {
                    if (sg == 0) mma16816_z(acc[mt][2 * p + q], a[mt], b[q]);
                    else         mma16816(acc[mt][2 * p + q], a[mt], b[q]);
                }
        }
    };

    // Consume one n-half of a tile whose first column is j0c.
    auto consume_half = [&](int j0c, int p) {
        if (j0c != i0 && j0c != pos_j0) {
            // FAST PATH: pure EX2 + FADD, register-independent of other half.
#pragma unroll
            for (int mt = 0; mt < 4; mt++)
#pragma unroll
                for (int e = 0; e < 4; e++)
                    rowacc[mt * 2 + (e >> 1)] +=
                        ex2f(acc[mt][2 * p][e]) + ex2f(acc[mt][2 * p + 1][e]);
        } else {
            const bool isdiag = (j0c == i0);
#pragma unroll
            for (int mt = 0; mt < 4; mt++)
#pragma unroll
                for (int e = 0; e < 4; e++) {
                    int row = i0 + 64 * wr + 16 * mt + (lane >> 2) + 8 * (e >> 1);
                    int special = isdiag ? row : ((row + B_) & (N_ - 1));
                    float racc = 0.0f;
#pragma unroll
                    for (int q = 0; q < 2; q++) {
                        int nt = 2 * p + q;
                        int col = j0c + 32 * wc + 8 * nt + 2 * (lane & 3) + (e & 1);
                        float t = acc[mt][nt][e];
                        if (isdiag) {
                            if (col != row) racc += ex2f(t);
                        } else {
                            racc += ex2f(t);
                            if (col == special) g_pos[row] = t;
                        }
                    }
                    rowacc[mt * 2 + (e >> 1)] += racc;
                }
        }
    };

    int j0_prev = 0;
    for (int jt = 0; jt < 8; jt++) {
        const int buf = jt & 1;
        asm volatile("cp.async.wait_group 0;" ::: "memory");
        __syncthreads();

        if (jt + 1 < 8) load_B(jt + 1, buf ^ 1);

        const int j0 = jbase + jt * 128;
        const uint32_t Bbase = Bb[buf];

        mma_pass(Bbase, 0);                     // writes nt0,1 (c=0 at sg0)
        if (jt > 0) consume_half(j0_prev, 1);   // EX2 prev nt2,3 -- overlaps
        mma_pass(Bbase, 1);                     // writes nt2,3
        consume_half(j0, 0);                    // EX2 this nt0,1 -- overlaps next
        j0_prev = j0;
    }
    consume_half(j0_prev, 1);                   // tail: last tile's nt2,3

#pragma unroll
    for (int idx = 0; idx < 8; idx++) {
        float v = rowacc[idx];
        v += __shfl_xor_sync(0xffffffffu, v, 1);
        v += __shfl_xor_sync(0xffffffffu, v, 2);
        if ((lane & 3) == 0) {
            int row = i0 + 64 * wr + 16 * (idx >> 1) + (lane >> 2) + 8 * (idx & 1);
            g_rowsum_part[(blockIdx.y * 4 + wc) * N_ + row] = v;
        }
    }
}

// ---------------------------------------------------------------------------
// Kernel 3a: per-CTA partial loss. pos is in base-2 units -> multiply by ln2.
// ---------------------------------------------------------------------------
__global__ __launch_bounds__(256) void finalize_part_kernel()
{
    __shared__ double red[256];
    const int tid = threadIdx.x;
    const int base = blockIdx.x * 128;
    double acc = 0.0;
    {
        int row = base + (tid & 127);
        int half = tid >> 7;
        float rs = 0.0f;
#pragma unroll
        for (int p = 0; p < 16; p++)
            rs += g_rowsum_part[(16 * half + p) * N_ + row];
        red[tid] = (double)rs;
    }
    __syncthreads();
    if (tid < 128) {
        int row = base + tid;
        float rs = (float)(red[tid] + red[tid + 128]);
        acc = (double)logf(rs) - (double)(g_pos[row] * LN2_);
    }
    __syncthreads();
    red[tid] = (tid < 128) ? acc : 0.0;
    __syncthreads();
    for (int s = 128; s > 0; s >>= 1) {
        if (tid < s) red[tid] += red[tid + s];
        __syncthreads();
    }
    if (tid == 0) g_loss_part[blockIdx.x] = red[0];
}

// ---------------------------------------------------------------------------
// Kernel 3b: sum 64 partials -> loss.
// ---------------------------------------------------------------------------
__global__ __launch_bounds__(64) void finalize_final_kernel(float* __restrict__ out)
{
    const int tid = threadIdx.x;
    double v = g_loss_part[tid];
#pragma unroll
    for (int m = 16; m > 0; m >>= 1)
        v += __shfl_xor_sync(0xffffffffu, v, m);
    __shared__ double wsum[2];
    if ((tid & 31) == 0) wsum[tid >> 5] = v;
    __syncthreads();
    if (tid == 0) out[0] = (float)((wsum[0] + wsum[1]) / (double)N_);
}

// ---------------------------------------------------------------------------
extern "C" void kernel_launch(void* const* d_in, const int* in_sizes, int n_in,
                              void* d_out, int out_size)
{
    const float* zi = (const float*)d_in[0];
    const float* zj = (const float*)d_in[1];
    const float* W  = (const float*)d_in[2];
    const float* b  = (const float*)d_in[3];
    float* out = (float*)d_out;

    static int attr_done = 0;
    if (!attr_done) {
        cudaFuncSetAttribute(gemm1_part_kernel,
                             cudaFuncAttributeMaxDynamicSharedMemorySize,
                             G1_SMEM_BYTES);
        cudaFuncSetAttribute(sim_rowsum_kernel,
                             cudaFuncAttributeMaxDynamicSharedMemorySize,
                             SIM_SMEM_BYTES);
        attr_done = 1;
    }

    wconv_kernel<<<128, 256>>>(W);
    gemm1_part_kernel<<<256, 256, G1_SMEM_BYTES>>>(zi, zj);
    hnorm_kernel<<<1024, 256>>>(b);
    sim_rowsum_kernel<<<dim3(64, 8), 256, SIM_SMEM_BYTES>>>();
    finalize_part_kernel<<<64, 256>>>();
    finalize_final_kernel<<<1, 64>>>(out);
}

// round 16
// speedup vs baseline: 1.1016x; 1.1016x over previous
#include <cuda_runtime.h>
#include <cuda_bf16.h>
#include <math.h>
#include <stdint.h>

// Problem constants
#define B_    4096
#define DIN_  2048
#define DOUT_ 128
#define N_    8192   // 2*B_

// zn pre-scale: dot(zn'_i, zn'_j) = (2/T)*log2(e)*cos_ij  (T=0.5)
// so exp(sim/T) = 2^dot -- epilogue needs only EX2.
#define ZN_SCALE 1.69864122f    // sqrt(2 * log2(e))
#define LN2_     0.69314718055994531f

// Scratch (device globals -- no allocation allowed)
__device__ __nv_bfloat16 g_znb[N_ * DOUT_];    // scaled normalized reps, bf16
__device__ __nv_bfloat16 g_wb[DOUT_ * DIN_];   // W in bf16
__device__ float g_h0[N_ * DOUT_];             // split-K partial 0
__device__ float g_h1[N_ * DOUT_];             // split-K partial 1
__device__ float g_rowsum_part[16 * N_];       // per-(jsplit,wc) partials
__device__ float g_pos[N_];                    // positive-pair logits (base-2)
__device__ double g_loss_part[64];             // per-CTA partial losses

__device__ __forceinline__ uint32_t sptr(const void* p) {
    return (uint32_t)__cvta_generic_to_shared(p);
}

__device__ __forceinline__ float ex2f(float x) {
    float r;
    asm("ex2.approx.ftz.f32 %0, %1;" : "=f"(r) : "f"(x));
    return r;
}

__device__ __forceinline__ void ldsm_x4(uint32_t addr, uint32_t& r0, uint32_t& r1,
                                        uint32_t& r2, uint32_t& r3) {
    asm volatile("ldmatrix.sync.aligned.m8n8.x4.shared.b16 {%0,%1,%2,%3}, [%4];"
                 : "=r"(r0), "=r"(r1), "=r"(r2), "=r"(r3) : "r"(addr));
}

__device__ __forceinline__ void mma16816(float* c, const uint32_t* a, const uint32_t* b) {
    asm volatile(
        "mma.sync.aligned.m16n8k16.row.col.f32.bf16.bf16.f32 "
        "{%0,%1,%2,%3}, {%4,%5,%6,%7}, {%8,%9}, {%0,%1,%2,%3};"
        : "+f"(c[0]), "+f"(c[1]), "+f"(c[2]), "+f"(c[3])
        : "r"(a[0]), "r"(a[1]), "r"(a[2]), "r"(a[3]), "r"(b[0]), "r"(b[1]));
}

// First-use form: d = a*b + 0.
__device__ __forceinline__ void mma16816_z(float* d, const uint32_t* a, const uint32_t* b) {
    asm volatile(
        "mma.sync.aligned.m16n8k16.row.col.f32.bf16.bf16.f32 "
        "{%0,%1,%2,%3}, {%4,%5,%6,%7}, {%8,%9}, {%10,%11,%12,%13};"
        : "=f"(d[0]), "=f"(d[1]), "=f"(d[2]), "=f"(d[3])
        : "r"(a[0]), "r"(a[1]), "r"(a[2]), "r"(a[3]), "r"(b[0]), "r"(b[1]),
          "f"(0.0f), "f"(0.0f), "f"(0.0f), "f"(0.0f));
}

__device__ __forceinline__ void cpa16(uint32_t smem_addr, const void* gptr) {
    asm volatile("cp.async.cg.shared.global.L2::128B [%0], [%1], 16;"
                 :: "r"(smem_addr), "l"(gptr) : "memory");
}

__device__ __forceinline__ void sts16(uint32_t addr, uint4 v) {
    asm volatile("st.shared.v4.b32 [%0], {%1,%2,%3,%4};"
                 :: "r"(addr), "r"(v.x), "r"(v.y), "r"(v.z), "r"(v.w) : "memory");
}

// ---------------------------------------------------------------------------
// Kernel 0: convert W (fp32) -> g_wb (bf16).
// ---------------------------------------------------------------------------
__global__ __launch_bounds__(256) void wconv_kernel(const float* __restrict__ W)
{
    int idx = blockIdx.x * 256 + threadIdx.x;
    const float4* src = (const float4*)W;
    float4 v0 = src[2 * idx];
    float4 v1 = src[2 * idx + 1];
    __nv_bfloat162 h[4];
    h[0] = __floats2bfloat162_rn(v0.x, v0.y);
    h[1] = __floats2bfloat162_rn(v0.z, v0.w);
    h[2] = __floats2bfloat162_rn(v1.x, v1.y);
    h[3] = __floats2bfloat162_rn(v1.z, v1.w);
    *(uint4*)&g_wb[idx * 8] = *(uint4*)h;
}

// ---------------------------------------------------------------------------
// Kernel 1: split-K=2 partial GEMM: Hpart = relu(Z) @ Wb[:, khalf]^T.
// ---------------------------------------------------------------------------
#define G1_SMEM_BYTES 99328

__global__ __launch_bounds__(256, 2) void gemm1_part_kernel(
    const float* __restrict__ zi, const float* __restrict__ zj)
{
    extern __shared__ __align__(16) unsigned char dynsm[];
    const uint32_t smraw = sptr(dynsm);
    const uint32_t smbase = (smraw + 1023) & ~1023u;
    const uint32_t As[2] = {smbase, smbase + 16384};
    const uint32_t Ws[2] = {smbase + 32768, smbase + 65536};

    const int tid = threadIdx.x;
    const int lane = tid & 31;
    const int warp = tid >> 5;
    const int tile = blockIdx.x & 127;
    const int khalf = blockIdx.x >> 7;
    const int kbase = khalf * 8;
    const int i0 = tile * 64;

    const float* Z = (i0 < B_) ? zi : zj;
    const int zr0 = (i0 < B_) ? i0 : (i0 - B_);

    float acc[4][2][4];
#pragma unroll
    for (int mt = 0; mt < 4; mt++)
#pragma unroll
        for (int nt = 0; nt < 2; nt++)
#pragma unroll
            for (int e = 0; e < 4; e++) acc[mt][nt][e] = 0.0f;

    float4 av[8];

    auto fetch_A = [&](int kc) {
#pragma unroll
        for (int it = 0; it < 4; it++) {
            int e = tid + it * 256;
            int r = e >> 4, c = e & 15;
            const float* src = &Z[(size_t)(zr0 + r) * DIN_ + kc * 128 + c * 8];
            av[2 * it]     = *(const float4*)src;
            av[2 * it + 1] = *(const float4*)(src + 4);
        }
    };
    auto store_A = [&](int stg) {
#pragma unroll
        for (int it = 0; it < 4; it++) {
            int e = tid + it * 256;
            int r = e >> 4, c = e & 15;
            float4 v0 = av[2 * it], v1 = av[2 * it + 1];
            __nv_bfloat162 h[4];
            h[0] = __floats2bfloat162_rn(fmaxf(v0.x, 0.f), fmaxf(v0.y, 0.f));
            h[1] = __floats2bfloat162_rn(fmaxf(v0.z, 0.f), fmaxf(v0.w, 0.f));
            h[2] = __floats2bfloat162_rn(fmaxf(v1.x, 0.f), fmaxf(v1.y, 0.f));
            h[3] = __floats2bfloat162_rn(fmaxf(v1.z, 0.f), fmaxf(v1.w, 0.f));
            sts16(As[stg] + r * 256 + ((c ^ (r & 7)) << 4), *(uint4*)h);
        }
    };
    auto load_W = [&](int kc, int stg) {
#pragma unroll
        for (int it = 0; it < 8; it++) {
            int e = tid + it * 256;
            int r = e >> 4, c = e & 15;
            cpa16(Ws[stg] + r * 256 + ((c ^ (r & 7)) << 4),
                  &g_wb[(size_t)r * DIN_ + kc * 128 + c * 8]);
        }
        asm volatile("cp.async.commit_group;" ::: "memory");
    };

    fetch_A(kbase);
    load_W(kbase, 0);
    store_A(0);

    for (int kc2 = 0; kc2 < 8; kc2++) {
        const int stg = kc2 & 1;
        asm volatile("cp.async.wait_group 0;" ::: "memory");
        __syncthreads();

        if (kc2 + 1 < 8) {
            fetch_A(kbase + kc2 + 1);
            load_W(kbase + kc2 + 1, stg ^ 1);
        }

        const uint32_t Abase = As[stg], Wbase = Ws[stg];
#pragma unroll
        for (int s = 0; s < 8; s++) {
            uint32_t a[4][4];
#pragma unroll
            for (int mt = 0; mt < 4; mt++) {
                int rloc = 16 * mt + (lane & 15);
                int ch = 2 * s + (lane >> 4);
                uint32_t ad = Abase + rloc * 256 + ((ch ^ (rloc & 7)) << 4);
                ldsm_x4(ad, a[mt][0], a[mt][1], a[mt][2], a[mt][3]);
            }
            uint32_t b[2][2];
            {
                int nloc = 16 * warp + (lane & 7) + ((lane >> 4) << 3);
                int ch = 2 * s + ((lane >> 3) & 1);
                uint32_t ad = Wbase + nloc * 256 + ((ch ^ (nloc & 7)) << 4);
                ldsm_x4(ad, b[0][0], b[0][1], b[1][0], b[1][1]);
            }
#pragma unroll
            for (int mt = 0; mt < 4; mt++)
#pragma unroll
                for (int nt = 0; nt < 2; nt++)
                    mma16816(acc[mt][nt], a[mt], b[nt]);
        }

        if (kc2 + 1 < 8) store_A(stg ^ 1);
    }

    float* Hp = khalf ? g_h1 : g_h0;
#pragma unroll
    for (int mt = 0; mt < 4; mt++)
#pragma unroll
        for (int nt = 0; nt < 2; nt++) {
            int r0 = i0 + 16 * mt + (lane >> 2);
            int c0 = 16 * warp + 8 * nt + 2 * (lane & 3);
            *(float2*)&Hp[(size_t)r0 * DOUT_ + c0] =
                make_float2(acc[mt][nt][0], acc[mt][nt][1]);
            *(float2*)&Hp[(size_t)(r0 + 8) * DOUT_ + c0] =
                make_float2(acc[mt][nt][2], acc[mt][nt][3]);
        }
}

// ---------------------------------------------------------------------------
// Kernel 1b: combine partials + bias, row-normalize, scale by ZN_SCALE.
// ---------------------------------------------------------------------------
__global__ __launch_bounds__(256) void hnorm_kernel(const float* __restrict__ bias)
{
    const int lane = threadIdx.x & 31;
    const int warp = threadIdx.x >> 5;
    const int row = blockIdx.x * 8 + warp;

    float hx[4];
    float ss = 0.0f;
#pragma unroll
    for (int q = 0; q < 2; q++) {
        int c = 2 * lane + 64 * q;
        float2 a = *(const float2*)&g_h0[(size_t)row * DOUT_ + c];
        float2 b = *(const float2*)&g_h1[(size_t)row * DOUT_ + c];
        float2 bb = *(const float2*)&bias[c];
        float x = a.x + b.x + bb.x;
        float y = a.y + b.y + bb.y;
        hx[2 * q] = x; hx[2 * q + 1] = y;
        ss += x * x + y * y;
    }
#pragma unroll
    for (int m = 16; m > 0; m >>= 1)
        ss += __shfl_xor_sync(0xffffffffu, ss, m);
    float inv = ZN_SCALE / fmaxf(sqrtf(ss), 1e-8f);
#pragma unroll
    for (int q = 0; q < 2; q++) {
        int c = 2 * lane + 64 * q;
        *(__nv_bfloat162*)&g_znb[(size_t)row * DOUT_ + c] =
            __floats2bfloat162_rn(hx[2 * q] * inv, hx[2 * q + 1] * inv);
    }
}

// ---------------------------------------------------------------------------
// Kernel 2: sim rowsums. 64-col j-subtiles, warps 4x2 (warp tile 32x32),
// ping-pong acc arrays: the sg-loop of subtile st fuses 4 EX2+FADD of
// subtile st-1's acc (independent registers -> overlaps the tensor pipe).
// Special (diag/pos) subtiles consumed via compare path, then poisoned to
// -30 so the unconditional fused EX2 adds ~2^-30 (negligible).
// ---------------------------------------------------------------------------
#define SIM_SMEM_BYTES 66560   // 1KB slack + A 32KB + 2 x B 16KB
#define NSUB 16                // 64-col subtiles per 1024-col split

__global__ __launch_bounds__(256, 2) void sim_rowsum_kernel()
{
    extern __shared__ __align__(16) unsigned char dynsm[];
    const uint32_t smraw = sptr(dynsm);
    const uint32_t smbase = (smraw + 1023) & ~1023u;
    const uint32_t Abase = smbase;
    const uint32_t Bb[2] = {smbase + 32768, smbase + 49152};

    const int tid = threadIdx.x;
    const int lane = tid & 31;
    const int warp = tid >> 5;
    const int wr = warp >> 1;      // 0..3 : rows 32*wr
    const int wc = warp & 1;       // 0..1 : cols 32*wc
    const int i0 = blockIdx.x * 128;
    const int jbase = blockIdx.y * 1024;
    const int pos_j0 = (i0 + B_) & (N_ - 1);   // 128-aligned

    // Load A tile (128 rows x 256B swizzled)
#pragma unroll
    for (int it = 0; it < 8; it++) {
        int e = tid + it * 256;
        int r = e >> 4, c = e & 15;
        uint4 v = *(const uint4*)&g_znb[(size_t)(i0 + r) * DOUT_ + c * 8];
        *(uint4*)(dynsm + (Abase - smraw) + r * 256 + ((c ^ (r & 7)) << 4)) = v;
    }

    // Hoisted B addressing (64-row subtiles: 4 cp.async per thread)
    const int br = tid >> 4, bc = tid & 15;
    const __nv_bfloat16* srcB0 = &g_znb[(size_t)(jbase + br) * DOUT_ + bc * 8];
    const uint32_t dstoff = (uint32_t)(br * 256 + ((bc ^ (br & 7)) << 4));

    auto load_B = [&](int st, int buf) {
        const __nv_bfloat16* s = srcB0 + (size_t)st * (64 * DOUT_);
        uint32_t d = Bb[buf] + dstoff;
#pragma unroll
        for (int it = 0; it < 4; it++) {
            cpa16(d, s);
            s += 16 * DOUT_;
            d += 16 * 256;
        }
        asm volatile("cp.async.commit_group;" ::: "memory");
    };

    load_B(0, 0);

    float rowacc[4] = {0.0f, 0.0f, 0.0f, 0.0f};
    float accA[2][4][4], accB[2][4][4];
#pragma unroll
    for (int mt = 0; mt < 2; mt++)
#pragma unroll
        for (int nt = 0; nt < 4; nt++)
#pragma unroll
            for (int e = 0; e < 4; e++) accB[mt][nt][e] = -30.0f;

    // Compare-path consume (diag/pos subtiles only), then poison to -30.
    auto consume_compare = [&](float (&p)[2][4][4], int j0c) {
        const bool isdiag = ((j0c & ~127) == i0);
#pragma unroll
        for (int mt = 0; mt < 2; mt++)
#pragma unroll
            for (int e = 0; e < 4; e++) {
                int row = i0 + 32 * wr + 16 * mt + (lane >> 2) + 8 * (e >> 1);
                int special = isdiag ? row : ((row + B_) & (N_ - 1));
                float racc = 0.0f;
#pragma unroll
                for (int nt = 0; nt < 4; nt++) {
                    int col = j0c + 32 * wc + 8 * nt + 2 * (lane & 3) + (e & 1);
                    float t = p[mt][nt][e];
                    if (isdiag) {
                        if (col != row) racc += ex2f(t);
                    } else {
                        racc += ex2f(t);
                        if (col == special) g_pos[row] = t;
                    }
                    p[mt][nt][e] = -30.0f;
                }
                rowacc[mt * 2 + (e >> 1)] += racc;
            }
    };

    // One subtile step: MMA into cur (c=0 at sg0), fused EX2 of prev.
    auto step = [&](int st, float (&cur)[2][4][4], float (&prev)[2][4][4]) {
        asm volatile("cp.async.wait_group 0;" ::: "memory");
        __syncthreads();
        if (st + 1 < NSUB) load_B(st + 1, (st + 1) & 1);

        const uint32_t Bbase = Bb[st & 1];

        // If prev subtile was special, consume it via compares (it then
        // holds -30 so the fused EX2 below adds ~0).
        if (st > 0) {
            int j0p = jbase + (st - 1) * 64;
            if (((j0p & ~127) == i0) || ((j0p & ~127) == pos_j0))
                consume_compare(prev, j0p);
        }

#pragma unroll
        for (int sg = 0; sg < 8; sg++) {
            uint32_t a[2][4];
#pragma unroll
            for (int mt = 0; mt < 2; mt++) {
                int rloc = 32 * wr + 16 * mt + (lane & 15);
                int ch = 2 * sg + (lane >> 4);
                uint32_t ad = Abase + rloc * 256 + ((ch ^ (rloc & 7)) << 4);
                ldsm_x4(ad, a[mt][0], a[mt][1], a[mt][2], a[mt][3]);
            }
            uint32_t b[4][2];
#pragma unroll
            for (int p = 0; p < 2; p++) {
                int nloc = 32 * wc + 16 * p + (lane & 7) + ((lane >> 4) << 3);
                int ch = 2 * sg + ((lane >> 3) & 1);
                uint32_t ad = Bbase + nloc * 256 + ((ch ^ (nloc & 7)) << 4);
                ldsm_x4(ad, b[2 * p][0], b[2 * p][1], b[2 * p + 1][0], b[2 * p + 1][1]);
            }
#pragma unroll
            for (int mt = 0; mt < 2; mt++)
#pragma unroll
                for (int nt = 0; nt < 4; nt++) {
                    if (sg == 0) mma16816_z(cur[mt][nt], a[mt], b[nt]);
                    else         mma16816(cur[mt][nt], a[mt], b[nt]);
                }
            // Fused: 4 EX2+FADD of prev (independent regs; overlaps MMA pipe)
#pragma unroll
            for (int q = 0; q < 4; q++) {
                int idx = sg * 4 + q;
                int mt = idx >> 4, rem = idx & 15;
                int nt = rem >> 2, e = rem & 3;
                rowacc[mt * 2 + (e >> 1)] += ex2f(prev[mt][nt][e]);
            }
        }
    };

    for (int st2 = 0; st2 < NSUB; st2 += 2) {
        step(st2,     accA, accB);
        step(st2 + 1, accB, accA);
    }

    // Tail: consume last subtile (st = NSUB-1, in accB)
    {
        int j0l = jbase + (NSUB - 1) * 64;
        if (((j0l & ~127) == i0) || ((j0l & ~127) == pos_j0)) {
            consume_compare(accB, j0l);
        } else {
#pragma unroll
            for (int mt = 0; mt < 2; mt++)
#pragma unroll
                for (int nt = 0; nt < 4; nt++)
#pragma unroll
                    for (int e = 0; e < 4; e++)
                        rowacc[mt * 2 + (e >> 1)] += ex2f(accB[mt][nt][e]);
        }
    }

#pragma unroll
    for (int idx = 0; idx < 4; idx++) {
        float v = rowacc[idx];
        v += __shfl_xor_sync(0xffffffffu, v, 1);
        v += __shfl_xor_sync(0xffffffffu, v, 2);
        if ((lane & 3) == 0) {
            int row = i0 + 32 * wr + 16 * (idx >> 1) + (lane >> 2) + 8 * (idx & 1);
            g_rowsum_part[(blockIdx.y * 2 + wc) * N_ + row] = v;
        }
    }
}

// ---------------------------------------------------------------------------
// Kernel 3a: per-CTA partial loss (16 partials/row). pos in base-2 -> x ln2.
// ---------------------------------------------------------------------------
__global__ __launch_bounds__(256) void finalize_part_kernel()
{
    __shared__ double red[256];
    const int tid = threadIdx.x;
    const int base = blockIdx.x * 128;
    double acc = 0.0;
    {
        int row = base + (tid & 127);
        int half = tid >> 7;
        float rs = 0.0f;
#pragma unroll
        for (int p = 0; p < 8; p++)
            rs += g_rowsum_part[(8 * half + p) * N_ + row];
        red[tid] = (double)rs;
    }
    __syncthreads();
    if (tid < 128) {
        int row = base + tid;
        float rs = (float)(red[tid] + red[tid + 128]);
        acc = (double)logf(rs) - (double)(g_pos[row] * LN2_);
    }
    __syncthreads();
    red[tid] = (tid < 128) ? acc : 0.0;
    __syncthreads();
    for (int s = 128; s > 0; s >>= 1) {
        if (tid < s) red[tid] += red[tid + s];
        __syncthreads();
    }
    if (tid == 0) g_loss_part[blockIdx.x] = red[0];
}

// ---------------------------------------------------------------------------
// Kernel 3b: sum 64 partials -> loss.
// ---------------------------------------------------------------------------
__global__ __launch_bounds__(64) void finalize_final_kernel(float* __restrict__ out)
{
    const int tid = threadIdx.x;
    double v = g_loss_part[tid];
#pragma unroll
    for (int m = 16; m > 0; m >>= 1)
        v += __shfl_xor_sync(0xffffffffu, v, m);
    __shared__ double wsum[2];
    if ((tid & 31) == 0) wsum[tid >> 5] = v;
    __syncthreads();
    if (tid == 0) out[0] = (float)((wsum[0] + wsum[1]) / (double)N_);
}

// ---------------------------------------------------------------------------
extern "C" void kernel_launch(void* const* d_in, const int* in_sizes, int n_in,
                              void* d_out, int out_size)
{
    const float* zi = (const float*)d_in[0];
    const float* zj = (const float*)d_in[1];
    const float* W  = (const float*)d_in[2];
    const float* b  = (const float*)d_in[3];
    float* out = (float*)d_out;

    static int attr_done = 0;
    if (!attr_done) {
        cudaFuncSetAttribute(gemm1_part_kernel,
                             cudaFuncAttributeMaxDynamicSharedMemorySize,
                             G1_SMEM_BYTES);
        cudaFuncSetAttribute(sim_rowsum_kernel,
                             cudaFuncAttributeMaxDynamicSharedMemorySize,
                             SIM_SMEM_BYTES);
        attr_done = 1;
    }

    wconv_kernel<<<128, 256>>>(W);
    gemm1_part_kernel<<<256, 256, G1_SMEM_BYTES>>>(zi, zj);
    hnorm_kernel<<<1024, 256>>>(b);
    sim_rowsum_kernel<<<dim3(64, 8), 256, SIM_SMEM_BYTES>>>();
    finalize_part_kernel<<<64, 256>>>();
    finalize_final_kernel<<<1, 64>>>(out);
}